// round 8
// baseline (speedup 1.0000x reference)
#include <cuda_runtime.h>
#include <cstdint>

#define N_NODES 10000
#define N_EDGES 640000
#define TE 256
#define TN 512

typedef uint32_t u32;

// ---------------- device scratch ----------------
__device__ float g_hagg[N_NODES * 128];
__device__ float g_cagg4[N_NODES * 4];   // xyz agg + count
__device__ float g_P[N_NODES * 128];     // h @ We1[0:128] + be1
__device__ float g_Q[N_NODES * 128];     // h @ We1[128:256]
__device__ float g_zb[128];              // stays zero
__device__ uint4 g_Bf2[8 * 512];         // (bh01, bh23, bl01, bl23)
__device__ uint2 g_Bf3[8 * 512];         // (bh01, bh23) hi-only

__device__ __forceinline__ float silu_f(float x) { return x / (1.0f + __expf(-x)); }

__device__ __forceinline__ u32 bf16x2_rn(float x0, float x1) {
    u32 r; asm("cvt.rn.bf16x2.f32 %0, %1, %2;" : "=r"(r) : "f"(x1), "f"(x0)); return r;
}
__device__ __forceinline__ u32 bf16x2_lo(float x0, float x1, u32 h) {
    float h0 = __uint_as_float(h << 16);
    float h1 = __uint_as_float(h & 0xffff0000u);
    return bf16x2_rn(x0 - h0, x1 - h1);
}
__device__ __forceinline__ u32 smem_u32(const void* p) {
    u32 a;
    asm("{ .reg .u64 t; cvta.to.shared.u64 t, %1; cvt.u32.u64 %0, t; }"
        : "=r"(a) : "l"(p));
    return a;
}
__device__ __forceinline__ void ldsm_x4(u32* r, u32 addr) {
    asm volatile("ldmatrix.sync.aligned.m8n8.x4.shared.b16 {%0,%1,%2,%3}, [%4];"
        : "=r"(r[0]), "=r"(r[1]), "=r"(r[2]), "=r"(r[3]) : "r"(addr));
}
__device__ __forceinline__ void red_v4(float* p, float4 v) {
    asm volatile("red.global.add.v4.f32 [%0], {%1,%2,%3,%4};"
        :: "l"(p), "f"(v.x), "f"(v.y), "f"(v.z), "f"(v.w) : "memory");
}

#define MMA_BF16(d, a0, a1, a2, a3, b0, b1)                                 \
    asm volatile(                                                           \
        "mma.sync.aligned.m16n8k16.row.col.f32.bf16.bf16.f32 "              \
        "{%0,%1,%2,%3},{%4,%5,%6,%7},{%8,%9},{%0,%1,%2,%3};"                \
        : "+f"((d)[0]), "+f"((d)[1]), "+f"((d)[2]), "+f"((d)[3])            \
        : "r"(a0), "r"(a1), "r"(a2), "r"(a3), "r"(b0), "r"(b1))

// ---------------- prep: We2/Wc1 -> bf16 fragments ----------------
__global__ void prep_kernel(const float* __restrict__ We2,
                            const float* __restrict__ Wc1)
{
    int i = blockIdx.x * blockDim.x + threadIdx.x;
    if (i >= 8192) return;
    const float* W = (i < 4096) ? We2 : Wc1;
    int idx = i & 4095;
    int c = idx >> 9, rem = idx & 511;
    int t = rem >> 5, l = rem & 31;
    int g = l >> 2, tig = l & 3;
    int n = t * 8 + g;
    int k0 = c * 16 + 2 * tig;
    float w0 = W[(k0    ) * 128 + n];
    float w1 = W[(k0 + 1) * 128 + n];
    float w2 = W[(k0 + 8) * 128 + n];
    float w3 = W[(k0 + 9) * 128 + n];
    u32 bh01 = bf16x2_rn(w0, w1), bh23 = bf16x2_rn(w2, w3);
    if (i < 4096) {
        g_Bf2[idx] = make_uint4(bh01, bh23,
                                bf16x2_lo(w0, w1, bh01), bf16x2_lo(w2, w3, bh23));
    } else {
        g_Bf3[idx] = make_uint2(bh01, bh23);
    }
}

__global__ void zero_kernel()
{
    int i = blockIdx.x * blockDim.x + threadIdx.x;
    int st = gridDim.x * blockDim.x;
    for (int k = i; k < N_NODES * 128; k += st) g_hagg[k] = 0.0f;
    for (int k = i; k < N_NODES * 4;   k += st) g_cagg4[k] = 0.0f;
}

// ---------------- scalar fp32 GEMM tile (512 threads, 64 rows) ----------------
template<int K, bool SILU>
__device__ __forceinline__ void gemm_tile(
    const float* __restrict__ sIn, int inStride,
    const float* __restrict__ W, const float* __restrict__ bias,
    float* __restrict__ sOut, int outStride, float* __restrict__ s_w)
{
    const int tx = threadIdx.x & 31;
    const int r0 = (threadIdx.x >> 5) * 4;
    float acc[4][4];
#pragma unroll
    for (int i = 0; i < 4; i++)
#pragma unroll
        for (int c = 0; c < 4; c++) acc[i][c] = 0.0f;

    for (int kc = 0; kc < K; kc += 16) {
        __syncthreads();
        {
            int t = threadIdx.x, r = t >> 5, c = t & 31;
            ((float4*)s_w)[r * 33 + c] = *((const float4*)(W + (size_t)(kc + r) * 128) + c);
        }
        __syncthreads();
#pragma unroll
        for (int kk = 0; kk < 16; kk += 4) {
            float4 av[4];
#pragma unroll
            for (int i = 0; i < 4; i++)
                av[i] = *(const float4*)&sIn[(r0 + i) * inStride + kc + kk];
#pragma unroll
            for (int q = 0; q < 4; q++) {
                float4 w = ((const float4*)s_w)[(kk + q) * 33 + tx];
#pragma unroll
                for (int i = 0; i < 4; i++) {
                    float a = (q == 0) ? av[i].x : (q == 1) ? av[i].y
                              : (q == 2) ? av[i].z : av[i].w;
                    acc[i][0] = fmaf(a, w.x, acc[i][0]);
                    acc[i][1] = fmaf(a, w.y, acc[i][1]);
                    acc[i][2] = fmaf(a, w.z, acc[i][2]);
                    acc[i][3] = fmaf(a, w.w, acc[i][3]);
                }
            }
        }
    }
    float4 b = *((const float4*)bias + tx);
#pragma unroll
    for (int i = 0; i < 4; i++) {
        float4 v;
        v.x = acc[i][0] + b.x; v.y = acc[i][1] + b.y;
        v.z = acc[i][2] + b.z; v.w = acc[i][3] + b.w;
        if (SILU) { v.x = silu_f(v.x); v.y = silu_f(v.y); v.z = silu_f(v.z); v.w = silu_f(v.w); }
        *(float4*)&sOut[(r0 + i) * outStride + tx * 4] = v;
    }
}

// ---------------- pre: P = h@We1_top + be1, Q = h@We1_bot ----------------
#define PRE_SMEM_BYTES ((64*132 + 16*33*4 + 64*132) * 4)
__global__ void __launch_bounds__(TN, 1)
pre_kernel(const float* __restrict__ h, const float* __restrict__ We1,
           const float* __restrict__ be1)
{
    extern __shared__ float smf[];
    float* s_in  = smf;
    float* s_w   = s_in + 64 * 132;
    float* s_out = s_w + 16 * 33 * 4;
    const int tid = threadIdx.x;
    const int n0  = blockIdx.x * 64;

    for (int idx = tid; idx < 64 * 128; idx += TN) {
        int r = idx >> 7, c = idx & 127, n = n0 + r;
        s_in[r * 132 + c] = (n < N_NODES) ? h[(size_t)n * 128 + c] : 0.0f;
    }
    gemm_tile<128, false>(s_in, 132, We1, be1, s_out, 132, s_w);
    __syncthreads();
    for (int idx = tid; idx < 64 * 128; idx += TN) {
        int r = idx >> 7, c = idx & 127, n = n0 + r;
        if (n < N_NODES) g_P[(size_t)n * 128 + c] = s_out[r * 132 + c];
    }
    __syncthreads();
    gemm_tile<128, false>(s_in, 132, We1 + 128 * 128, g_zb, s_out, 132, s_w);
    __syncthreads();
    for (int idx = tid; idx < 64 * 128; idx += TN) {
        int r = idx >> 7, c = idx & 127, n = n0 + r;
        if (n < N_NODES) g_Q[(size_t)n * 128 + c] = s_out[r * 132 + c];
    }
}

// ---------------- bf16 mma cores (ldmatrix A) ----------------
template<int KC>
__device__ __forceinline__ void mma_gemm_bf16(
    u32 AhiA, u32 AloA, int SA,
    const uint4* __restrict__ Bf, float acc[2][4][4],
    int m0, int ntb, int lane)
{
    int arow = (m0 + (lane & 15)) * SA + ((lane >> 4) << 2);
    u32 h0 = AhiA + arow * 4, h1 = h0 + 16 * SA * 4;
    u32 l0 = AloA + arow * 4, l1 = l0 + 16 * SA * 4;

    uint4 bf[2][4];
#pragma unroll
    for (int nt = 0; nt < 4; nt++)
        bf[0][nt] = __ldg(Bf + (ntb + nt) * 32 + lane);

#pragma unroll 2
    for (int c = 0; c < KC; c++) {
        int cur = c & 1, nxt = cur ^ 1;
        if (c + 1 < KC) {
#pragma unroll
            for (int nt = 0; nt < 4; nt++)
                bf[nxt][nt] = __ldg(Bf + ((c + 1) * 16 + ntb + nt) * 32 + lane);
        }
        u32 ah[2][4], al[2][4];
        ldsm_x4(ah[0], h0 + c * 32);
        ldsm_x4(ah[1], h1 + c * 32);
        ldsm_x4(al[0], l0 + c * 32);
        ldsm_x4(al[1], l1 + c * 32);
#pragma unroll
        for (int nt = 0; nt < 4; nt++) {
            u32 bh0 = bf[cur][nt].x, bh1 = bf[cur][nt].y;
            u32 bl0 = bf[cur][nt].z, bl1 = bf[cur][nt].w;
#pragma unroll
            for (int mt = 0; mt < 2; mt++) {
                MMA_BF16(acc[mt][nt], ah[mt][0], ah[mt][1], ah[mt][2], ah[mt][3], bh0, bh1);
                MMA_BF16(acc[mt][nt], al[mt][0], al[mt][1], al[mt][2], al[mt][3], bh0, bh1);
                MMA_BF16(acc[mt][nt], ah[mt][0], ah[mt][1], ah[mt][2], ah[mt][3], bl0, bl1);
            }
        }
    }
}

template<int KC>
__device__ __forceinline__ void mma_gemm_bf16_2t(
    u32 AhiA, u32 AloA, int SA,
    const uint2* __restrict__ Bf, float acc[2][4][4],
    int m0, int ntb, int lane)
{
    int arow = (m0 + (lane & 15)) * SA + ((lane >> 4) << 2);
    u32 h0 = AhiA + arow * 4, h1 = h0 + 16 * SA * 4;
    u32 l0 = AloA + arow * 4, l1 = l0 + 16 * SA * 4;

    uint2 bf[2][4];
#pragma unroll
    for (int nt = 0; nt < 4; nt++)
        bf[0][nt] = __ldg(Bf + (ntb + nt) * 32 + lane);

#pragma unroll 2
    for (int c = 0; c < KC; c++) {
        int cur = c & 1, nxt = cur ^ 1;
        if (c + 1 < KC) {
#pragma unroll
            for (int nt = 0; nt < 4; nt++)
                bf[nxt][nt] = __ldg(Bf + ((c + 1) * 16 + ntb + nt) * 32 + lane);
        }
        u32 ah[2][4], al[2][4];
        ldsm_x4(ah[0], h0 + c * 32);
        ldsm_x4(ah[1], h1 + c * 32);
        ldsm_x4(al[0], l0 + c * 32);
        ldsm_x4(al[1], l1 + c * 32);
#pragma unroll
        for (int nt = 0; nt < 4; nt++) {
            u32 bh0 = bf[cur][nt].x, bh1 = bf[cur][nt].y;
#pragma unroll
            for (int mt = 0; mt < 2; mt++) {
                MMA_BF16(acc[mt][nt], ah[mt][0], ah[mt][1], ah[mt][2], ah[mt][3], bh0, bh1);
                MMA_BF16(acc[mt][nt], al[mt][0], al[mt][1], al[mt][2], al[mt][3], bh0, bh1);
            }
        }
    }
}

// ---------------- SMEM layout (u32 units) ----------------
#define SH 68
#define OFF_HIDH 0
#define OFF_HIDL 4352
#define OFF_EFH  8704
#define OFF_EFL  13056
#define OFF_MISC 17408
#define SMEM_EDGE_U32 (OFF_MISC + 1152)
#define SMEM_EDGE_BYTES (SMEM_EDGE_U32 * 4)

__global__ void __launch_bounds__(TE, 2)
edge_kernel(const float* __restrict__ y, const int* __restrict__ ei,
            const float* __restrict__ w256,
            const float* __restrict__ be2, const float* __restrict__ bc1,
            const float* __restrict__ Wc2)
{
    extern __shared__ u32 smu[];
    u32* hidH = smu + OFF_HIDH;
    u32* hidL = smu + OFF_HIDL;
    float* s_ef32 = (float*)(smu + OFF_HIDH);   // alias over dead hid (needs 8448)
    float* s_w256 = (float*)(smu + OFF_MISC);
    float* s_be2  = s_w256 + 128;
    float* s_bc1  = s_be2 + 128;
    float* s_wc2  = s_bc1 + 128;
    float* s_rad  = s_wc2 + 128;          // [64]
    float* s_diff = s_rad + 64;           // [64][3]
    float* s_part = s_diff + 192;         // [4][64]
    int*   s_row  = (int*)(s_part + 256); // [64]
    int*   s_col  = s_row + 64;           // [64]

    const int tid  = threadIdx.x;
    const int lane = tid & 31;
    const int wid  = tid >> 5;
    const int g    = lane >> 2;
    const int tig  = lane & 3;
    const int mw   = wid >> 2;
    const int nw   = wid & 3;
    const int m0   = mw * 32;
    const int ntb  = nw * 4;
    const int e0g  = blockIdx.x * 64;

    const u32 smb   = smem_u32(smu);
    const u32 hidHa = smb + OFF_HIDH * 4;
    const u32 hidLa = smb + OFF_HIDL * 4;
    const u32 efHa  = smb + OFF_EFH * 4;
    const u32 efLa  = smb + OFF_EFL * 4;
    u32* efH = smu + OFF_EFH;
    u32* efL = smu + OFF_EFL;

    if (tid < 64) {
        int r = ei[e0g + tid], c = ei[N_EDGES + e0g + tid];
        s_row[tid] = r; s_col[tid] = c;
        float dx = y[r*3+0]-y[c*3+0], dy = y[r*3+1]-y[c*3+1], dz = y[r*3+2]-y[c*3+2];
        s_diff[tid*3+0] = dx; s_diff[tid*3+1] = dy; s_diff[tid*3+2] = dz;
        s_rad[tid] = dx*dx + dy*dy + dz*dz;
    }
    if (tid < 128) {
        s_w256[tid] = w256[tid];
        s_be2[tid] = be2[tid]; s_bc1[tid] = bc1[tid]; s_wc2[tid] = Wc2[tid];
    }
    __syncthreads();

    // ---- fused former-GEMM1: hid = silu(P[row] + Q[col] + rad*w256) ----
#pragma unroll 2
    for (int t = wid; t < 64; t += 8) {
        int rnode = s_row[t], cnode = s_col[t];
        float4 p = __ldg((const float4*)(g_P + (size_t)rnode * 128) + lane);
        float4 q = __ldg((const float4*)(g_Q + (size_t)cnode * 128) + lane);
        float rad = s_rad[t];
        float4 w = *(const float4*)&s_w256[lane * 4];
        float v0 = silu_f(p.x + q.x + rad * w.x);
        float v1 = silu_f(p.y + q.y + rad * w.y);
        float v2 = silu_f(p.z + q.z + rad * w.z);
        float v3 = silu_f(p.w + q.w + rad * w.w);
        u32 h0 = bf16x2_rn(v0, v1), h1 = bf16x2_rn(v2, v3);
        int o = t * SH + lane * 2;
        *(uint2*)&hidH[o] = make_uint2(h0, h1);
        *(uint2*)&hidL[o] = make_uint2(bf16x2_lo(v0, v1, h0), bf16x2_lo(v2, v3, h1));
    }
    __syncthreads();

    float acc[2][4][4];
#define ZACC() do { _Pragma("unroll") for (int a_ = 0; a_ < 2; a_++) \
    _Pragma("unroll") for (int b_ = 0; b_ < 4; b_++) \
    _Pragma("unroll") for (int c_ = 0; c_ < 4; c_++) acc[a_][b_][c_] = 0.0f; } while (0)

    // ================= GEMM2: hid @ We2 (3-term) =================
    ZACC();
    mma_gemm_bf16<8>(hidHa, hidLa, SH, g_Bf2, acc, m0, ntb, lane);
    __syncthreads();   // hid reads done before s_ef32 overlays it
#pragma unroll
    for (int mt = 0; mt < 2; mt++) {
        int ra = m0 + mt * 16 + g, rb = ra + 8;
#pragma unroll
        for (int nt = 0; nt < 4; nt++) {
            int col = (ntb + nt) * 8 + 2 * tig;
            int uc  = (ntb + nt) * 4 + tig;
            float b0 = s_be2[col], b1 = s_be2[col + 1];
            float v0 = silu_f(acc[mt][nt][0] + b0), v1 = silu_f(acc[mt][nt][1] + b1);
            float v2 = silu_f(acc[mt][nt][2] + b0), v3 = silu_f(acc[mt][nt][3] + b1);
            u32 ha = bf16x2_rn(v0, v1), hb = bf16x2_rn(v2, v3);
            efH[ra * SH + uc] = ha; efL[ra * SH + uc] = bf16x2_lo(v0, v1, ha);
            efH[rb * SH + uc] = hb; efL[rb * SH + uc] = bf16x2_lo(v2, v3, hb);
            *(float2*)&s_ef32[ra * 132 + col] = make_float2(v0, v1);
            *(float2*)&s_ef32[rb * 132 + col] = make_float2(v2, v3);
        }
    }
    __syncthreads();

    // ---- hagg scatter: fire-and-forget vectorized reductions ----
#pragma unroll
    for (int it = 0; it < 8; it++) {
        int idx = it * TE + tid;
        int e = idx >> 5, c4 = idx & 31;
        float4 v = *(const float4*)&s_ef32[e * 132 + c4 * 4];
        red_v4(&g_hagg[(size_t)s_row[e] * 128 + c4 * 4], v);
    }

    // ================= GEMM3: ef @ Wc1 (2-term) =================
    ZACC();
    mma_gemm_bf16_2t<8>(efHa, efLa, SH, g_Bf3, acc, m0, ntb, lane);
    {
        float p[4] = {0.f, 0.f, 0.f, 0.f};
#pragma unroll
        for (int mt = 0; mt < 2; mt++) {
#pragma unroll
            for (int nt = 0; nt < 4; nt++) {
                int col = (ntb + nt) * 8 + 2 * tig;
                float b0 = s_bc1[col], b1 = s_bc1[col + 1];
                float w0 = s_wc2[col], w1 = s_wc2[col + 1];
                p[mt*2+0] += silu_f(acc[mt][nt][0] + b0) * w0
                           + silu_f(acc[mt][nt][1] + b1) * w1;
                p[mt*2+1] += silu_f(acc[mt][nt][2] + b0) * w0
                           + silu_f(acc[mt][nt][3] + b1) * w1;
            }
        }
#pragma unroll
        for (int i = 0; i < 4; i++) {
            p[i] += __shfl_xor_sync(0xffffffffu, p[i], 1);
            p[i] += __shfl_xor_sync(0xffffffffu, p[i], 2);
        }
        if (tig == 0) {
#pragma unroll
            for (int mt = 0; mt < 2; mt++) {
                s_part[nw * 64 + m0 + mt * 16 + g]     = p[mt*2+0];
                s_part[nw * 64 + m0 + mt * 16 + g + 8] = p[mt*2+1];
            }
        }
    }
    __syncthreads();

    if (tid < 64) {
        float s = s_part[tid] + s_part[64 + tid] + s_part[128 + tid] + s_part[192 + tid];
        float4 v = make_float4(s_diff[tid*3+0] * s, s_diff[tid*3+1] * s,
                               s_diff[tid*3+2] * s, 1.0f);
        red_v4(&g_cagg4[s_row[tid] * 4], v);
    }
#undef ZACC
}

// ---------------- node kernel ----------------
#define NB 64
#define INS 264
#define HIS 132
#define SMEM_NODE_BYTES ((NB*INS + 16*33*4 + NB*HIS) * 4)

__global__ void __launch_bounds__(TN, 1)
node_kernel(const float* __restrict__ h, const float* __restrict__ y,
            const float* __restrict__ Wn1, const float* __restrict__ bn1,
            const float* __restrict__ Wn2, const float* __restrict__ bn2,
            float* __restrict__ out_h, float* __restrict__ out_y)
{
    extern __shared__ float smf[];
    float* s_in  = smf;
    float* s_w   = s_in + NB * INS;
    float* s_hid = s_w + 16 * 33 * 4;

    const int tid = threadIdx.x, lane = tid & 31, wid = tid >> 5;
    const int n0 = blockIdx.x * NB;

    for (int t = wid; t < 2 * NB; t += 16) {
        int e = t >> 1, half = t & 1, n = n0 + e;
        float4 v = make_float4(0.f, 0.f, 0.f, 0.f);
        if (n < N_NODES) {
            const float* src = half ? (g_hagg + (size_t)n * 128) : (h + (size_t)n * 128);
            v = *((const float4*)src + lane);
        }
        *(float4*)&s_in[e * INS + half * 128 + lane * 4] = v;
    }

    gemm_tile<256, true>(s_in, INS, Wn1, bn1, s_hid, HIS, s_w);
    gemm_tile<128, false>(s_hid, HIS, Wn2, bn2, s_in + 128, INS, s_w);
    __syncthreads();

    for (int idx = tid; idx < NB * 128; idx += TN) {
        int e = idx >> 7, j = idx & 127, n = n0 + e;
        if (n < N_NODES)
            out_h[(size_t)n * 128 + j] = s_in[e * INS + j] + s_in[e * INS + 128 + j];
    }
    if (tid < NB) {
        int n = n0 + tid;
        if (n < N_NODES) {
            float c = g_cagg4[n * 4 + 3]; c = (c < 1.0f) ? 1.0f : c;
            out_y[n*3+0] = y[n*3+0] + g_cagg4[n*4+0] / c;
            out_y[n*3+1] = y[n*3+1] + g_cagg4[n*4+1] / c;
            out_y[n*3+2] = y[n*3+2] + g_cagg4[n*4+2] / c;
        }
    }
}

extern "C" void kernel_launch(void* const* d_in, const int* in_sizes, int n_in,
                              void* d_out, int out_size)
{
    const float* h   = (const float*)d_in[0];
    const float* y   = (const float*)d_in[1];
    const int*   ei  = (const int*)d_in[2];
    const float* We1 = (const float*)d_in[3];
    const float* be1 = (const float*)d_in[4];
    const float* We2 = (const float*)d_in[5];
    const float* be2 = (const float*)d_in[6];
    const float* Wc1 = (const float*)d_in[7];
    const float* bc1 = (const float*)d_in[8];
    const float* Wc2 = (const float*)d_in[9];
    const float* Wn1 = (const float*)d_in[10];
    const float* bn1 = (const float*)d_in[11];
    const float* Wn2 = (const float*)d_in[12];
    const float* bn2 = (const float*)d_in[13];

    float* out_h = (float*)d_out;
    float* out_y = out_h + (size_t)N_NODES * 128;

    cudaFuncSetAttribute(edge_kernel, cudaFuncAttributeMaxDynamicSharedMemorySize,
                         SMEM_EDGE_BYTES);
    cudaFuncSetAttribute(node_kernel, cudaFuncAttributeMaxDynamicSharedMemorySize,
                         SMEM_NODE_BYTES);
    cudaFuncSetAttribute(pre_kernel, cudaFuncAttributeMaxDynamicSharedMemorySize,
                         PRE_SMEM_BYTES);

    zero_kernel<<<512, TE>>>();
    prep_kernel<<<32, 256>>>(We2, Wc1);
    pre_kernel<<<(N_NODES + 63) / 64, TN, PRE_SMEM_BYTES>>>(h, We1, be1);

    edge_kernel<<<N_EDGES / 64, TE, SMEM_EDGE_BYTES>>>(
        y, ei, We1 + 256 * 128, be2, bc1, Wc2);

    node_kernel<<<(N_NODES + NB - 1) / NB, TN, SMEM_NODE_BYTES>>>(
        h, y, Wn1, bn1, Wn2, bn2, out_h, out_y);
}

// round 9
// speedup vs baseline: 1.3399x; 1.3399x over previous
#include <cuda_runtime.h>
#include <cstdint>

#define N_NODES 10000
#define N_EDGES 640000
#define TE 256
#define TN 512

typedef uint32_t u32;

// ---------------- device scratch ----------------
__device__ float g_hagg[N_NODES * 128];
__device__ float g_cagg4[N_NODES * 4];   // xyz agg + count
__device__ float g_P[N_NODES * 128];
__device__ float g_Q[N_NODES * 128];
__device__ float g_zb[128];
__device__ uint4 g_Bf2[8 * 512];         // We2 3-term
__device__ uint2 g_Bf3[8 * 512];         // Wc1 hi-only
__device__ uint4 g_Bfn1[16 * 512];       // Wn1 3-term (K=256)
__device__ uint4 g_Bfn2[8 * 512];        // Wn2 3-term

__device__ __forceinline__ float silu_f(float x) { return x / (1.0f + __expf(-x)); }

__device__ __forceinline__ u32 bf16x2_rn(float x0, float x1) {
    u32 r; asm("cvt.rn.bf16x2.f32 %0, %1, %2;" : "=r"(r) : "f"(x1), "f"(x0)); return r;
}
__device__ __forceinline__ u32 bf16x2_lo(float x0, float x1, u32 h) {
    float h0 = __uint_as_float(h << 16);
    float h1 = __uint_as_float(h & 0xffff0000u);
    return bf16x2_rn(x0 - h0, x1 - h1);
}
__device__ __forceinline__ u32 smem_u32(const void* p) {
    u32 a;
    asm("{ .reg .u64 t; cvta.to.shared.u64 t, %1; cvt.u32.u64 %0, t; }"
        : "=r"(a) : "l"(p));
    return a;
}
__device__ __forceinline__ void ldsm_x4(u32* r, u32 addr) {
    asm volatile("ldmatrix.sync.aligned.m8n8.x4.shared.b16 {%0,%1,%2,%3}, [%4];"
        : "=r"(r[0]), "=r"(r[1]), "=r"(r[2]), "=r"(r[3]) : "r"(addr));
}
__device__ __forceinline__ void red_v4(float* p, float4 v) {
    asm volatile("red.global.add.v4.f32 [%0], {%1,%2,%3,%4};"
        :: "l"(p), "f"(v.x), "f"(v.y), "f"(v.z), "f"(v.w) : "memory");
}

#define MMA_BF16(d, a0, a1, a2, a3, b0, b1)                                 \
    asm volatile(                                                           \
        "mma.sync.aligned.m16n8k16.row.col.f32.bf16.bf16.f32 "              \
        "{%0,%1,%2,%3},{%4,%5,%6,%7},{%8,%9},{%0,%1,%2,%3};"                \
        : "+f"((d)[0]), "+f"((d)[1]), "+f"((d)[2]), "+f"((d)[3])            \
        : "r"(a0), "r"(a1), "r"(a2), "r"(a3), "r"(b0), "r"(b1))

// ---------------- prep: all weights -> bf16 fragments ----------------
__global__ void prep_kernel(const float* __restrict__ We2,
                            const float* __restrict__ Wc1,
                            const float* __restrict__ Wn1,
                            const float* __restrict__ Wn2)
{
    int i = blockIdx.x * blockDim.x + threadIdx.x;
    const float* W; int idx, mode;
    if (i < 4096)        { W = We2; idx = i;         mode = 0; }
    else if (i < 8192)   { W = Wc1; idx = i - 4096;  mode = 1; }
    else if (i < 16384)  { W = Wn1; idx = i - 8192;  mode = 2; }
    else if (i < 20480)  { W = Wn2; idx = i - 16384; mode = 3; }
    else return;

    int c = idx >> 9, rem = idx & 511;
    int t = rem >> 5, l = rem & 31;
    int g = l >> 2, tig = l & 3;
    int n = t * 8 + g;
    int k0 = c * 16 + 2 * tig;
    float w0 = W[(k0    ) * 128 + n];
    float w1 = W[(k0 + 1) * 128 + n];
    float w2 = W[(k0 + 8) * 128 + n];
    float w3 = W[(k0 + 9) * 128 + n];
    u32 bh01 = bf16x2_rn(w0, w1), bh23 = bf16x2_rn(w2, w3);
    u32 bl01 = bf16x2_lo(w0, w1, bh01), bl23 = bf16x2_lo(w2, w3, bh23);
    if (mode == 0)      g_Bf2[idx]  = make_uint4(bh01, bh23, bl01, bl23);
    else if (mode == 1) g_Bf3[idx]  = make_uint2(bh01, bh23);
    else if (mode == 2) g_Bfn1[idx] = make_uint4(bh01, bh23, bl01, bl23);
    else                g_Bfn2[idx] = make_uint4(bh01, bh23, bl01, bl23);
}

__global__ void zero_kernel()
{
    int i = blockIdx.x * blockDim.x + threadIdx.x;
    int st = gridDim.x * blockDim.x;
    for (int k = i; k < N_NODES * 128; k += st) g_hagg[k] = 0.0f;
    for (int k = i; k < N_NODES * 4;   k += st) g_cagg4[k] = 0.0f;
}

// ---------------- scalar fp32 GEMM tile (pre_kernel only) ----------------
template<int K, bool SILU>
__device__ __forceinline__ void gemm_tile(
    const float* __restrict__ sIn, int inStride,
    const float* __restrict__ W, const float* __restrict__ bias,
    float* __restrict__ sOut, int outStride, float* __restrict__ s_w)
{
    const int tx = threadIdx.x & 31;
    const int r0 = (threadIdx.x >> 5) * 4;
    float acc[4][4];
#pragma unroll
    for (int i = 0; i < 4; i++)
#pragma unroll
        for (int c = 0; c < 4; c++) acc[i][c] = 0.0f;

    for (int kc = 0; kc < K; kc += 16) {
        __syncthreads();
        {
            int t = threadIdx.x, r = t >> 5, c = t & 31;
            ((float4*)s_w)[r * 33 + c] = *((const float4*)(W + (size_t)(kc + r) * 128) + c);
        }
        __syncthreads();
#pragma unroll
        for (int kk = 0; kk < 16; kk += 4) {
            float4 av[4];
#pragma unroll
            for (int i = 0; i < 4; i++)
                av[i] = *(const float4*)&sIn[(r0 + i) * inStride + kc + kk];
#pragma unroll
            for (int q = 0; q < 4; q++) {
                float4 w = ((const float4*)s_w)[(kk + q) * 33 + tx];
#pragma unroll
                for (int i = 0; i < 4; i++) {
                    float a = (q == 0) ? av[i].x : (q == 1) ? av[i].y
                              : (q == 2) ? av[i].z : av[i].w;
                    acc[i][0] = fmaf(a, w.x, acc[i][0]);
                    acc[i][1] = fmaf(a, w.y, acc[i][1]);
                    acc[i][2] = fmaf(a, w.z, acc[i][2]);
                    acc[i][3] = fmaf(a, w.w, acc[i][3]);
                }
            }
        }
    }
    float4 b = *((const float4*)bias + tx);
#pragma unroll
    for (int i = 0; i < 4; i++) {
        float4 v;
        v.x = acc[i][0] + b.x; v.y = acc[i][1] + b.y;
        v.z = acc[i][2] + b.z; v.w = acc[i][3] + b.w;
        if (SILU) { v.x = silu_f(v.x); v.y = silu_f(v.y); v.z = silu_f(v.z); v.w = silu_f(v.w); }
        *(float4*)&sOut[(r0 + i) * outStride + tx * 4] = v;
    }
}

// ---------------- pre: P = h@We1_top + be1, Q = h@We1_bot ----------------
#define PRE_SMEM_BYTES ((64*132 + 16*33*4 + 64*132) * 4)
__global__ void __launch_bounds__(TN, 1)
pre_kernel(const float* __restrict__ h, const float* __restrict__ We1,
           const float* __restrict__ be1)
{
    extern __shared__ float smf[];
    float* s_in  = smf;
    float* s_w   = s_in + 64 * 132;
    float* s_out = s_w + 16 * 33 * 4;
    const int tid = threadIdx.x;
    const int n0  = blockIdx.x * 64;

    for (int idx = tid; idx < 64 * 128; idx += TN) {
        int r = idx >> 7, c = idx & 127, n = n0 + r;
        s_in[r * 132 + c] = (n < N_NODES) ? h[(size_t)n * 128 + c] : 0.0f;
    }
    gemm_tile<128, false>(s_in, 132, We1, be1, s_out, 132, s_w);
    __syncthreads();
    for (int idx = tid; idx < 64 * 128; idx += TN) {
        int r = idx >> 7, c = idx & 127, n = n0 + r;
        if (n < N_NODES) g_P[(size_t)n * 128 + c] = s_out[r * 132 + c];
    }
    __syncthreads();
    gemm_tile<128, false>(s_in, 132, We1 + 128 * 128, g_zb, s_out, 132, s_w);
    __syncthreads();
    for (int idx = tid; idx < 64 * 128; idx += TN) {
        int r = idx >> 7, c = idx & 127, n = n0 + r;
        if (n < N_NODES) g_Q[(size_t)n * 128 + c] = s_out[r * 132 + c];
    }
}

// ---------------- bf16 mma cores (single-buffered B) ----------------
template<int KC>
__device__ __forceinline__ void mma3(
    u32 AhiA, u32 AloA, int SA,
    const uint4* __restrict__ Bf, float acc[2][4][4],
    int m0, int ntb, int lane)
{
    int arow = (m0 + (lane & 15)) * SA + ((lane >> 4) << 2);
    u32 h0 = AhiA + arow * 4, h1 = h0 + 16 * SA * 4;
    u32 l0 = AloA + arow * 4, l1 = l0 + 16 * SA * 4;
#pragma unroll
    for (int c = 0; c < KC; c++) {
        uint4 bf[4];
#pragma unroll
        for (int nt = 0; nt < 4; nt++)
            bf[nt] = __ldg(Bf + (c * 16 + ntb + nt) * 32 + lane);
        u32 ah[2][4], al[2][4];
        ldsm_x4(ah[0], h0 + c * 32);
        ldsm_x4(ah[1], h1 + c * 32);
        ldsm_x4(al[0], l0 + c * 32);
        ldsm_x4(al[1], l1 + c * 32);
#pragma unroll
        for (int nt = 0; nt < 4; nt++) {
#pragma unroll
            for (int mt = 0; mt < 2; mt++) {
                MMA_BF16(acc[mt][nt], ah[mt][0], ah[mt][1], ah[mt][2], ah[mt][3],
                         bf[nt].x, bf[nt].y);
                MMA_BF16(acc[mt][nt], al[mt][0], al[mt][1], al[mt][2], al[mt][3],
                         bf[nt].x, bf[nt].y);
                MMA_BF16(acc[mt][nt], ah[mt][0], ah[mt][1], ah[mt][2], ah[mt][3],
                         bf[nt].z, bf[nt].w);
            }
        }
    }
}

template<int KC>
__device__ __forceinline__ void mma2t(
    u32 AhiA, u32 AloA, int SA,
    const uint2* __restrict__ Bf, float acc[2][4][4],
    int m0, int ntb, int lane)
{
    int arow = (m0 + (lane & 15)) * SA + ((lane >> 4) << 2);
    u32 h0 = AhiA + arow * 4, h1 = h0 + 16 * SA * 4;
    u32 l0 = AloA + arow * 4, l1 = l0 + 16 * SA * 4;
#pragma unroll
    for (int c = 0; c < KC; c++) {
        uint2 bf[4];
#pragma unroll
        for (int nt = 0; nt < 4; nt++)
            bf[nt] = __ldg(Bf + (c * 16 + ntb + nt) * 32 + lane);
        u32 ah[2][4], al[2][4];
        ldsm_x4(ah[0], h0 + c * 32);
        ldsm_x4(ah[1], h1 + c * 32);
        ldsm_x4(al[0], l0 + c * 32);
        ldsm_x4(al[1], l1 + c * 32);
#pragma unroll
        for (int nt = 0; nt < 4; nt++) {
#pragma unroll
            for (int mt = 0; mt < 2; mt++) {
                MMA_BF16(acc[mt][nt], ah[mt][0], ah[mt][1], ah[mt][2], ah[mt][3],
                         bf[nt].x, bf[nt].y);
                MMA_BF16(acc[mt][nt], al[mt][0], al[mt][1], al[mt][2], al[mt][3],
                         bf[nt].x, bf[nt].y);
            }
        }
    }
}

#define ZACC(acc) do { _Pragma("unroll") for (int a_ = 0; a_ < 2; a_++) \
    _Pragma("unroll") for (int b_ = 0; b_ < 4; b_++) \
    _Pragma("unroll") for (int c_ = 0; c_ < 4; c_++) acc[a_][b_][c_] = 0.0f; } while (0)

// ---------------- edge kernel ----------------
#define SH 68
#define OFF_HIDH 0
#define OFF_HIDL 4352
#define OFF_EFH  8704
#define OFF_EFL  13056
#define OFF_MISC 17408
#define SMEM_EDGE_U32 (OFF_MISC + 1152)
#define SMEM_EDGE_BYTES (SMEM_EDGE_U32 * 4)

__global__ void __launch_bounds__(TE, 3)
edge_kernel(const float* __restrict__ y, const int* __restrict__ ei,
            const float* __restrict__ w256,
            const float* __restrict__ be2, const float* __restrict__ bc1,
            const float* __restrict__ Wc2)
{
    extern __shared__ u32 smu[];
    u32* hidH = smu + OFF_HIDH;
    u32* hidL = smu + OFF_HIDL;
    float* s_ef32 = (float*)(smu + OFF_HIDH);
    float* s_w256 = (float*)(smu + OFF_MISC);
    float* s_be2  = s_w256 + 128;
    float* s_bc1  = s_be2 + 128;
    float* s_wc2  = s_bc1 + 128;
    float* s_rad  = s_wc2 + 128;
    float* s_diff = s_rad + 64;
    float* s_part = s_diff + 192;
    int*   s_row  = (int*)(s_part + 256);
    int*   s_col  = s_row + 64;

    const int tid  = threadIdx.x;
    const int lane = tid & 31;
    const int wid  = tid >> 5;
    const int g    = lane >> 2;
    const int tig  = lane & 3;
    const int mw   = wid >> 2;
    const int nw   = wid & 3;
    const int m0   = mw * 32;
    const int ntb  = nw * 4;
    const int e0g  = blockIdx.x * 64;

    const u32 smb   = smem_u32(smu);
    const u32 hidHa = smb + OFF_HIDH * 4;
    const u32 hidLa = smb + OFF_HIDL * 4;
    const u32 efHa  = smb + OFF_EFH * 4;
    const u32 efLa  = smb + OFF_EFL * 4;
    u32* efH = smu + OFF_EFH;
    u32* efL = smu + OFF_EFL;

    if (tid < 64) {
        int r = ei[e0g + tid], c = ei[N_EDGES + e0g + tid];
        s_row[tid] = r; s_col[tid] = c;
        float dx = y[r*3+0]-y[c*3+0], dy = y[r*3+1]-y[c*3+1], dz = y[r*3+2]-y[c*3+2];
        s_diff[tid*3+0] = dx; s_diff[tid*3+1] = dy; s_diff[tid*3+2] = dz;
        s_rad[tid] = dx*dx + dy*dy + dz*dz;
    }
    if (tid < 128) {
        s_w256[tid] = w256[tid];
        s_be2[tid] = be2[tid]; s_bc1[tid] = bc1[tid]; s_wc2[tid] = Wc2[tid];
    }
    __syncthreads();

    // ---- fused former-GEMM1: hid = silu(P[row] + Q[col] + rad*w256) ----
#pragma unroll 2
    for (int t = wid; t < 64; t += 8) {
        int rnode = s_row[t], cnode = s_col[t];
        float4 p = __ldg((const float4*)(g_P + (size_t)rnode * 128) + lane);
        float4 q = __ldg((const float4*)(g_Q + (size_t)cnode * 128) + lane);
        float rad = s_rad[t];
        float4 w = *(const float4*)&s_w256[lane * 4];
        float v0 = silu_f(p.x + q.x + rad * w.x);
        float v1 = silu_f(p.y + q.y + rad * w.y);
        float v2 = silu_f(p.z + q.z + rad * w.z);
        float v3 = silu_f(p.w + q.w + rad * w.w);
        u32 h0 = bf16x2_rn(v0, v1), h1 = bf16x2_rn(v2, v3);
        int o = t * SH + lane * 2;
        *(uint2*)&hidH[o] = make_uint2(h0, h1);
        *(uint2*)&hidL[o] = make_uint2(bf16x2_lo(v0, v1, h0), bf16x2_lo(v2, v3, h1));
    }
    __syncthreads();

    float acc[2][4][4];

    // ---- GEMM2: hid @ We2 (3-term) ----
    ZACC(acc);
    mma3<8>(hidHa, hidLa, SH, g_Bf2, acc, m0, ntb, lane);
    __syncthreads();
#pragma unroll
    for (int mt = 0; mt < 2; mt++) {
        int ra = m0 + mt * 16 + g, rb = ra + 8;
#pragma unroll
        for (int nt = 0; nt < 4; nt++) {
            int col = (ntb + nt) * 8 + 2 * tig;
            int uc  = (ntb + nt) * 4 + tig;
            float b0 = s_be2[col], b1 = s_be2[col + 1];
            float v0 = silu_f(acc[mt][nt][0] + b0), v1 = silu_f(acc[mt][nt][1] + b1);
            float v2 = silu_f(acc[mt][nt][2] + b0), v3 = silu_f(acc[mt][nt][3] + b1);
            u32 ha = bf16x2_rn(v0, v1), hb = bf16x2_rn(v2, v3);
            efH[ra * SH + uc] = ha; efL[ra * SH + uc] = bf16x2_lo(v0, v1, ha);
            efH[rb * SH + uc] = hb; efL[rb * SH + uc] = bf16x2_lo(v2, v3, hb);
            *(float2*)&s_ef32[ra * 132 + col] = make_float2(v0, v1);
            *(float2*)&s_ef32[rb * 132 + col] = make_float2(v2, v3);
        }
    }
    __syncthreads();

    // ---- hagg scatter (fire-and-forget red.v4) ----
#pragma unroll
    for (int it = 0; it < 8; it++) {
        int idx = it * TE + tid;
        int e = idx >> 5, c4 = idx & 31;
        float4 v = *(const float4*)&s_ef32[e * 132 + c4 * 4];
        red_v4(&g_hagg[(size_t)s_row[e] * 128 + c4 * 4], v);
    }

    // ---- GEMM3: ef @ Wc1 (2-term) ----
    ZACC(acc);
    mma2t<8>(efHa, efLa, SH, g_Bf3, acc, m0, ntb, lane);
    {
        float p[4] = {0.f, 0.f, 0.f, 0.f};
#pragma unroll
        for (int mt = 0; mt < 2; mt++) {
#pragma unroll
            for (int nt = 0; nt < 4; nt++) {
                int col = (ntb + nt) * 8 + 2 * tig;
                float b0 = s_bc1[col], b1 = s_bc1[col + 1];
                float w0 = s_wc2[col], w1 = s_wc2[col + 1];
                p[mt*2+0] += silu_f(acc[mt][nt][0] + b0) * w0
                           + silu_f(acc[mt][nt][1] + b1) * w1;
                p[mt*2+1] += silu_f(acc[mt][nt][2] + b0) * w0
                           + silu_f(acc[mt][nt][3] + b1) * w1;
            }
        }
#pragma unroll
        for (int i = 0; i < 4; i++) {
            p[i] += __shfl_xor_sync(0xffffffffu, p[i], 1);
            p[i] += __shfl_xor_sync(0xffffffffu, p[i], 2);
        }
        if (tig == 0) {
#pragma unroll
            for (int mt = 0; mt < 2; mt++) {
                s_part[nw * 64 + m0 + mt * 16 + g]     = p[mt*2+0];
                s_part[nw * 64 + m0 + mt * 16 + g + 8] = p[mt*2+1];
            }
        }
    }
    __syncthreads();

    if (tid < 64) {
        float s = s_part[tid] + s_part[64 + tid] + s_part[128 + tid] + s_part[192 + tid];
        float4 v = make_float4(s_diff[tid*3+0] * s, s_diff[tid*3+1] * s,
                               s_diff[tid*3+2] * s, 1.0f);
        red_v4(&g_cagg4[s_row[tid] * 4], v);
    }
}

// ---------------- node kernel: bf16 mma ----------------
#define SHN 132
#define NOFF_AHI 0
#define NOFF_ALO 8448
#define NOFF_HH  16896
#define NOFF_HL  21248
#define NOFF_MISC 25600
#define SMEM_NODE_U32 (NOFF_MISC + 256)
#define SMEM_NODE_BYTES (SMEM_NODE_U32 * 4)

__global__ void __launch_bounds__(TE, 1)
node_mma_kernel(const float* __restrict__ h, const float* __restrict__ y,
                const float* __restrict__ bn1, const float* __restrict__ bn2,
                float* __restrict__ out_h, float* __restrict__ out_y)
{
    extern __shared__ u32 smu[];
    u32* AhiN = smu + NOFF_AHI;
    u32* AloN = smu + NOFF_ALO;
    u32* hidH = smu + NOFF_HH;
    u32* hidL = smu + NOFF_HL;
    float* s_bn1 = (float*)(smu + NOFF_MISC);
    float* s_bn2 = s_bn1 + 128;

    const int tid  = threadIdx.x;
    const int lane = tid & 31;
    const int wid  = tid >> 5;
    const int g    = lane >> 2;
    const int tig  = lane & 3;
    const int mw   = wid >> 2;
    const int nw   = wid & 3;
    const int m0   = mw * 32;
    const int ntb  = nw * 4;
    const int n0   = blockIdx.x * 64;

    const u32 smb = smem_u32(smu);
    const u32 AhiA = smb + NOFF_AHI * 4;
    const u32 AloA = smb + NOFF_ALO * 4;
    const u32 hHa  = smb + NOFF_HH * 4;
    const u32 hLa  = smb + NOFF_HL * 4;

    if (tid < 128) { s_bn1[tid] = bn1[tid]; s_bn2[tid] = bn2[tid]; }

    // gather [h | hagg] -> bf16 hi/lo (K=256 -> 128 u32 per row)
    for (int t = wid; t < 128; t += 8) {
        int r = t >> 1, half = t & 1, n = n0 + r;
        float4 v = make_float4(0.f, 0.f, 0.f, 0.f);
        if (n < N_NODES) {
            const float* src = half ? (g_hagg + (size_t)n * 128) : (h + (size_t)n * 128);
            v = __ldg((const float4*)src + lane);
        }
        u32 h0 = bf16x2_rn(v.x, v.y), h1 = bf16x2_rn(v.z, v.w);
        int o = r * SHN + half * 64 + lane * 2;
        *(uint2*)&AhiN[o] = make_uint2(h0, h1);
        *(uint2*)&AloN[o] = make_uint2(bf16x2_lo(v.x, v.y, h0), bf16x2_lo(v.z, v.w, h1));
    }
    __syncthreads();

    float acc[2][4][4];

    // GEMM1: [h|hagg] @ Wn1 (K=256, 3-term) -> hid
    ZACC(acc);
    mma3<16>(AhiA, AloA, SHN, g_Bfn1, acc, m0, ntb, lane);
#pragma unroll
    for (int mt = 0; mt < 2; mt++) {
        int ra = m0 + mt * 16 + g, rb = ra + 8;
#pragma unroll
        for (int nt = 0; nt < 4; nt++) {
            int col = (ntb + nt) * 8 + 2 * tig;
            int uc  = (ntb + nt) * 4 + tig;
            float b0 = s_bn1[col], b1 = s_bn1[col + 1];
            float v0 = silu_f(acc[mt][nt][0] + b0), v1 = silu_f(acc[mt][nt][1] + b1);
            float v2 = silu_f(acc[mt][nt][2] + b0), v3 = silu_f(acc[mt][nt][3] + b1);
            u32 ha = bf16x2_rn(v0, v1), hb = bf16x2_rn(v2, v3);
            hidH[ra * SH + uc] = ha; hidL[ra * SH + uc] = bf16x2_lo(v0, v1, ha);
            hidH[rb * SH + uc] = hb; hidL[rb * SH + uc] = bf16x2_lo(v2, v3, hb);
        }
    }
    __syncthreads();

    // GEMM2: hid @ Wn2 (3-term) + bn2 + residual -> out_h
    ZACC(acc);
    mma3<8>(hHa, hLa, SH, g_Bfn2, acc, m0, ntb, lane);
#pragma unroll
    for (int mt = 0; mt < 2; mt++) {
        int ra = m0 + mt * 16 + g, rb = ra + 8;
        int na = n0 + ra, nb = n0 + rb;
#pragma unroll
        for (int nt = 0; nt < 4; nt++) {
            int col = (ntb + nt) * 8 + 2 * tig;
            float b0 = s_bn2[col], b1 = s_bn2[col + 1];
            if (na < N_NODES) {
                float2 hh = __ldg((const float2*)(h + (size_t)na * 128 + col));
                *(float2*)&out_h[(size_t)na * 128 + col] =
                    make_float2(acc[mt][nt][0] + b0 + hh.x, acc[mt][nt][1] + b1 + hh.y);
            }
            if (nb < N_NODES) {
                float2 hh = __ldg((const float2*)(h + (size_t)nb * 128 + col));
                *(float2*)&out_h[(size_t)nb * 128 + col] =
                    make_float2(acc[mt][nt][2] + b0 + hh.x, acc[mt][nt][3] + b1 + hh.y);
            }
        }
    }

    if (tid < 64) {
        int n = n0 + tid;
        if (n < N_NODES) {
            float c = g_cagg4[n * 4 + 3]; c = (c < 1.0f) ? 1.0f : c;
            out_y[n*3+0] = y[n*3+0] + g_cagg4[n*4+0] / c;
            out_y[n*3+1] = y[n*3+1] + g_cagg4[n*4+1] / c;
            out_y[n*3+2] = y[n*3+2] + g_cagg4[n*4+2] / c;
        }
    }
}

extern "C" void kernel_launch(void* const* d_in, const int* in_sizes, int n_in,
                              void* d_out, int out_size)
{
    const float* h   = (const float*)d_in[0];
    const float* y   = (const float*)d_in[1];
    const int*   ei  = (const int*)d_in[2];
    const float* We1 = (const float*)d_in[3];
    const float* be1 = (const float*)d_in[4];
    const float* We2 = (const float*)d_in[5];
    const float* be2 = (const float*)d_in[6];
    const float* Wc1 = (const float*)d_in[7];
    const float* bc1 = (const float*)d_in[8];
    const float* Wc2 = (const float*)d_in[9];
    const float* Wn1 = (const float*)d_in[10];
    const float* bn1 = (const float*)d_in[11];
    const float* Wn2 = (const float*)d_in[12];
    const float* bn2 = (const float*)d_in[13];

    float* out_h = (float*)d_out;
    float* out_y = out_h + (size_t)N_NODES * 128;

    cudaFuncSetAttribute(edge_kernel, cudaFuncAttributeMaxDynamicSharedMemorySize,
                         SMEM_EDGE_BYTES);
    cudaFuncSetAttribute(node_mma_kernel, cudaFuncAttributeMaxDynamicSharedMemorySize,
                         SMEM_NODE_BYTES);
    cudaFuncSetAttribute(pre_kernel, cudaFuncAttributeMaxDynamicSharedMemorySize,
                         PRE_SMEM_BYTES);

    zero_kernel<<<512, TE>>>();
    prep_kernel<<<80, 256>>>(We2, Wc1, Wn1, Wn2);
    pre_kernel<<<(N_NODES + 63) / 64, TN, PRE_SMEM_BYTES>>>(h, We1, be1);

    edge_kernel<<<N_EDGES / 64, TE, SMEM_EDGE_BYTES>>>(
        y, ei, We1 + 256 * 128, be2, bc1, Wc2);

    node_mma_kernel<<<(N_NODES + 63) / 64, TE, SMEM_NODE_BYTES>>>(
        h, y, bn1, bn2, out_h, out_y);
}

// round 10
// speedup vs baseline: 1.3999x; 1.0447x over previous
#include <cuda_runtime.h>
#include <cstdint>

#define N_NODES 10000
#define N_EDGES 640000
#define TE 256
#define TN 512

typedef uint32_t u32;

// ---------------- device scratch ----------------
__device__ float g_hagg[N_NODES * 128];
__device__ float g_cagg4[N_NODES * 4];
__device__ float g_P[N_NODES * 128];
__device__ float g_Q[N_NODES * 128];
__device__ float g_zb[128];
__device__ uint4 g_Bf2[8 * 512];         // We2 3-term
__device__ uint2 g_Bf3[8 * 512];         // Wc1 hi-only
__device__ uint4 g_Bfn1[16 * 512];       // Wn1 3-term (K=256)
__device__ uint4 g_Bfn2[8 * 512];        // Wn2 3-term

__device__ __forceinline__ float silu_f(float x) { return x / (1.0f + __expf(-x)); }

__device__ __forceinline__ u32 bf16x2_rn(float x0, float x1) {
    u32 r; asm("cvt.rn.bf16x2.f32 %0, %1, %2;" : "=r"(r) : "f"(x1), "f"(x0)); return r;
}
__device__ __forceinline__ u32 bf16x2_lo(float x0, float x1, u32 h) {
    float h0 = __uint_as_float(h << 16);
    float h1 = __uint_as_float(h & 0xffff0000u);
    return bf16x2_rn(x0 - h0, x1 - h1);
}
__device__ __forceinline__ u32 smem_u32(const void* p) {
    u32 a;
    asm("{ .reg .u64 t; cvta.to.shared.u64 t, %1; cvt.u32.u64 %0, t; }"
        : "=r"(a) : "l"(p));
    return a;
}
__device__ __forceinline__ void ldsm_x4(u32* r, u32 addr) {
    asm volatile("ldmatrix.sync.aligned.m8n8.x4.shared.b16 {%0,%1,%2,%3}, [%4];"
        : "=r"(r[0]), "=r"(r[1]), "=r"(r[2]), "=r"(r[3]) : "r"(addr));
}
__device__ __forceinline__ void red_v4(float* p, float4 v) {
    asm volatile("red.global.add.v4.f32 [%0], {%1,%2,%3,%4};"
        :: "l"(p), "f"(v.x), "f"(v.y), "f"(v.z), "f"(v.w) : "memory");
}
__device__ __forceinline__ void red_v2(float* p, float a, float b) {
    asm volatile("red.global.add.v2.f32 [%0], {%1,%2};"
        :: "l"(p), "f"(a), "f"(b) : "memory");
}

#define MMA_BF16(d, a0, a1, a2, a3, b0, b1)                                 \
    asm volatile(                                                           \
        "mma.sync.aligned.m16n8k16.row.col.f32.bf16.bf16.f32 "              \
        "{%0,%1,%2,%3},{%4,%5,%6,%7},{%8,%9},{%0,%1,%2,%3};"                \
        : "+f"((d)[0]), "+f"((d)[1]), "+f"((d)[2]), "+f"((d)[3])            \
        : "r"(a0), "r"(a1), "r"(a2), "r"(a3), "r"(b0), "r"(b1))

// ---------------- prep: weights -> bf16 fragments ----------------
__global__ void prep_kernel(const float* __restrict__ We2,
                            const float* __restrict__ Wc1,
                            const float* __restrict__ Wn1,
                            const float* __restrict__ Wn2)
{
    int i = blockIdx.x * blockDim.x + threadIdx.x;
    const float* W; int idx, mode;
    if (i < 4096)        { W = We2; idx = i;         mode = 0; }
    else if (i < 8192)   { W = Wc1; idx = i - 4096;  mode = 1; }
    else if (i < 16384)  { W = Wn1; idx = i - 8192;  mode = 2; }
    else if (i < 20480)  { W = Wn2; idx = i - 16384; mode = 3; }
    else return;

    int c = idx >> 9, rem = idx & 511;
    int t = rem >> 5, l = rem & 31;
    int g = l >> 2, tig = l & 3;
    int n = t * 8 + g;
    int k0 = c * 16 + 2 * tig;
    float w0 = W[(k0    ) * 128 + n];
    float w1 = W[(k0 + 1) * 128 + n];
    float w2 = W[(k0 + 8) * 128 + n];
    float w3 = W[(k0 + 9) * 128 + n];
    u32 bh01 = bf16x2_rn(w0, w1), bh23 = bf16x2_rn(w2, w3);
    u32 bl01 = bf16x2_lo(w0, w1, bh01), bl23 = bf16x2_lo(w2, w3, bh23);
    if (mode == 0)      g_Bf2[idx]  = make_uint4(bh01, bh23, bl01, bl23);
    else if (mode == 1) g_Bf3[idx]  = make_uint2(bh01, bh23);
    else if (mode == 2) g_Bfn1[idx] = make_uint4(bh01, bh23, bl01, bl23);
    else                g_Bfn2[idx] = make_uint4(bh01, bh23, bl01, bl23);
}

__global__ void zero_kernel()
{
    int i = blockIdx.x * blockDim.x + threadIdx.x;
    int st = gridDim.x * blockDim.x;
    for (int k = i; k < N_NODES * 128; k += st) g_hagg[k] = 0.0f;
    for (int k = i; k < N_NODES * 4;   k += st) g_cagg4[k] = 0.0f;
}

// ---------------- scalar fp32 GEMM tile (pre_kernel only) ----------------
template<int K, bool SILU>
__device__ __forceinline__ void gemm_tile(
    const float* __restrict__ sIn, int inStride,
    const float* __restrict__ W, const float* __restrict__ bias,
    float* __restrict__ sOut, int outStride, float* __restrict__ s_w)
{
    const int tx = threadIdx.x & 31;
    const int r0 = (threadIdx.x >> 5) * 4;
    float acc[4][4];
#pragma unroll
    for (int i = 0; i < 4; i++)
#pragma unroll
        for (int c = 0; c < 4; c++) acc[i][c] = 0.0f;

    for (int kc = 0; kc < K; kc += 16) {
        __syncthreads();
        {
            int t = threadIdx.x, r = t >> 5, c = t & 31;
            ((float4*)s_w)[r * 33 + c] = *((const float4*)(W + (size_t)(kc + r) * 128) + c);
        }
        __syncthreads();
#pragma unroll
        for (int kk = 0; kk < 16; kk += 4) {
            float4 av[4];
#pragma unroll
            for (int i = 0; i < 4; i++)
                av[i] = *(const float4*)&sIn[(r0 + i) * inStride + kc + kk];
#pragma unroll
            for (int q = 0; q < 4; q++) {
                float4 w = ((const float4*)s_w)[(kk + q) * 33 + tx];
#pragma unroll
                for (int i = 0; i < 4; i++) {
                    float a = (q == 0) ? av[i].x : (q == 1) ? av[i].y
                              : (q == 2) ? av[i].z : av[i].w;
                    acc[i][0] = fmaf(a, w.x, acc[i][0]);
                    acc[i][1] = fmaf(a, w.y, acc[i][1]);
                    acc[i][2] = fmaf(a, w.z, acc[i][2]);
                    acc[i][3] = fmaf(a, w.w, acc[i][3]);
                }
            }
        }
    }
    float4 b = *((const float4*)bias + tx);
#pragma unroll
    for (int i = 0; i < 4; i++) {
        float4 v;
        v.x = acc[i][0] + b.x; v.y = acc[i][1] + b.y;
        v.z = acc[i][2] + b.z; v.w = acc[i][3] + b.w;
        if (SILU) { v.x = silu_f(v.x); v.y = silu_f(v.y); v.z = silu_f(v.z); v.w = silu_f(v.w); }
        *(float4*)&sOut[(r0 + i) * outStride + tx * 4] = v;
    }
}

// ---------------- pre: P = h@We1_top + be1, Q = h@We1_bot ----------------
#define PRE_SMEM_BYTES ((64*132 + 16*33*4 + 64*132) * 4)
__global__ void __launch_bounds__(TN, 1)
pre_kernel(const float* __restrict__ h, const float* __restrict__ We1,
           const float* __restrict__ be1)
{
    extern __shared__ float smf[];
    float* s_in  = smf;
    float* s_w   = s_in + 64 * 132;
    float* s_out = s_w + 16 * 33 * 4;
    const int tid = threadIdx.x;
    const int n0  = blockIdx.x * 64;

    for (int idx = tid; idx < 64 * 128; idx += TN) {
        int r = idx >> 7, c = idx & 127, n = n0 + r;
        s_in[r * 132 + c] = (n < N_NODES) ? h[(size_t)n * 128 + c] : 0.0f;
    }
    gemm_tile<128, false>(s_in, 132, We1, be1, s_out, 132, s_w);
    __syncthreads();
    for (int idx = tid; idx < 64 * 128; idx += TN) {
        int r = idx >> 7, c = idx & 127, n = n0 + r;
        if (n < N_NODES) g_P[(size_t)n * 128 + c] = s_out[r * 132 + c];
    }
    __syncthreads();
    gemm_tile<128, false>(s_in, 132, We1 + 128 * 128, g_zb, s_out, 132, s_w);
    __syncthreads();
    for (int idx = tid; idx < 64 * 128; idx += TN) {
        int r = idx >> 7, c = idx & 127, n = n0 + r;
        if (n < N_NODES) g_Q[(size_t)n * 128 + c] = s_out[r * 132 + c];
    }
}

// ---------------- bf16 mma cores ----------------
template<int KC>
__device__ __forceinline__ void mma3(
    u32 AhiA, u32 AloA, int SA,
    const uint4* __restrict__ Bf, float acc[2][4][4],
    int m0, int ntb, int lane)
{
    int arow = (m0 + (lane & 15)) * SA + ((lane >> 4) << 2);
    u32 h0 = AhiA + arow * 4, h1 = h0 + 16 * SA * 4;
    u32 l0 = AloA + arow * 4, l1 = l0 + 16 * SA * 4;
#pragma unroll
    for (int c = 0; c < KC; c++) {
        uint4 bf[4];
#pragma unroll
        for (int nt = 0; nt < 4; nt++)
            bf[nt] = __ldg(Bf + (c * 16 + ntb + nt) * 32 + lane);
        u32 ah[2][4], al[2][4];
        ldsm_x4(ah[0], h0 + c * 32);
        ldsm_x4(ah[1], h1 + c * 32);
        ldsm_x4(al[0], l0 + c * 32);
        ldsm_x4(al[1], l1 + c * 32);
#pragma unroll
        for (int nt = 0; nt < 4; nt++) {
#pragma unroll
            for (int mt = 0; mt < 2; mt++) {
                MMA_BF16(acc[mt][nt], ah[mt][0], ah[mt][1], ah[mt][2], ah[mt][3],
                         bf[nt].x, bf[nt].y);
                MMA_BF16(acc[mt][nt], al[mt][0], al[mt][1], al[mt][2], al[mt][3],
                         bf[nt].x, bf[nt].y);
                MMA_BF16(acc[mt][nt], ah[mt][0], ah[mt][1], ah[mt][2], ah[mt][3],
                         bf[nt].z, bf[nt].w);
            }
        }
    }
}

// 1-term: A hi only, B hi only (coord path)
template<int KC>
__device__ __forceinline__ void mma1t(
    u32 AhiA, int SA,
    const uint2* __restrict__ Bf, float acc[2][4][4],
    int m0, int ntb, int lane)
{
    int arow = (m0 + (lane & 15)) * SA + ((lane >> 4) << 2);
    u32 h0 = AhiA + arow * 4, h1 = h0 + 16 * SA * 4;
#pragma unroll
    for (int c = 0; c < KC; c++) {
        uint2 bf[4];
#pragma unroll
        for (int nt = 0; nt < 4; nt++)
            bf[nt] = __ldg(Bf + (c * 16 + ntb + nt) * 32 + lane);
        u32 ah[2][4];
        ldsm_x4(ah[0], h0 + c * 32);
        ldsm_x4(ah[1], h1 + c * 32);
#pragma unroll
        for (int nt = 0; nt < 4; nt++) {
#pragma unroll
            for (int mt = 0; mt < 2; mt++) {
                MMA_BF16(acc[mt][nt], ah[mt][0], ah[mt][1], ah[mt][2], ah[mt][3],
                         bf[nt].x, bf[nt].y);
            }
        }
    }
}

#define ZACC(acc) do { _Pragma("unroll") for (int a_ = 0; a_ < 2; a_++) \
    _Pragma("unroll") for (int b_ = 0; b_ < 4; b_++) \
    _Pragma("unroll") for (int c_ = 0; c_ < 4; c_++) acc[a_][b_][c_] = 0.0f; } while (0)

// ---------------- edge kernel ----------------
#define SH 68
#define OFF_HIDH 0
#define OFF_HIDL 4352
#define OFF_EFH  8704
#define OFF_MISC 13056
#define SMEM_EDGE_U32 (OFF_MISC + 1152)
#define SMEM_EDGE_BYTES (SMEM_EDGE_U32 * 4)

__global__ void __launch_bounds__(TE, 3)
edge_kernel(const float* __restrict__ y, const int* __restrict__ ei,
            const float* __restrict__ w256,
            const float* __restrict__ be2, const float* __restrict__ bc1,
            const float* __restrict__ Wc2)
{
    extern __shared__ u32 smu[];
    u32* hidH = smu + OFF_HIDH;
    u32* hidL = smu + OFF_HIDL;
    u32* efH  = smu + OFF_EFH;
    float* s_w256 = (float*)(smu + OFF_MISC);
    float* s_be2  = s_w256 + 128;
    float* s_bc1  = s_be2 + 128;
    float* s_wc2  = s_bc1 + 128;
    float* s_rad  = s_wc2 + 128;
    float* s_diff = s_rad + 64;
    float* s_part = s_diff + 192;
    int*   s_row  = (int*)(s_part + 256);
    int*   s_col  = s_row + 64;

    const int tid  = threadIdx.x;
    const int lane = tid & 31;
    const int wid  = tid >> 5;
    const int g    = lane >> 2;
    const int tig  = lane & 3;
    const int mw   = wid >> 2;
    const int nw   = wid & 3;
    const int m0   = mw * 32;
    const int ntb  = nw * 4;
    const int e0g  = blockIdx.x * 64;

    const u32 smb   = smem_u32(smu);
    const u32 hidHa = smb + OFF_HIDH * 4;
    const u32 hidLa = smb + OFF_HIDL * 4;
    const u32 efHa  = smb + OFF_EFH * 4;

    if (tid < 64) {
        int r = ei[e0g + tid], c = ei[N_EDGES + e0g + tid];
        s_row[tid] = r; s_col[tid] = c;
        float dx = y[r*3+0]-y[c*3+0], dy = y[r*3+1]-y[c*3+1], dz = y[r*3+2]-y[c*3+2];
        s_diff[tid*3+0] = dx; s_diff[tid*3+1] = dy; s_diff[tid*3+2] = dz;
        s_rad[tid] = dx*dx + dy*dy + dz*dz;
    }
    if (tid < 128) {
        s_w256[tid] = w256[tid];
        s_be2[tid] = be2[tid]; s_bc1[tid] = bc1[tid]; s_wc2[tid] = Wc2[tid];
    }
    __syncthreads();

    // ---- fused former-GEMM1: hid = silu(P[row] + Q[col] + rad*w256) ----
#pragma unroll 2
    for (int t = wid; t < 64; t += 8) {
        int rnode = s_row[t], cnode = s_col[t];
        float4 p = __ldg((const float4*)(g_P + (size_t)rnode * 128) + lane);
        float4 q = __ldg((const float4*)(g_Q + (size_t)cnode * 128) + lane);
        float rad = s_rad[t];
        float4 w = *(const float4*)&s_w256[lane * 4];
        float v0 = silu_f(p.x + q.x + rad * w.x);
        float v1 = silu_f(p.y + q.y + rad * w.y);
        float v2 = silu_f(p.z + q.z + rad * w.z);
        float v3 = silu_f(p.w + q.w + rad * w.w);
        u32 h0 = bf16x2_rn(v0, v1), h1 = bf16x2_rn(v2, v3);
        int o = t * SH + lane * 2;
        *(uint2*)&hidH[o] = make_uint2(h0, h1);
        *(uint2*)&hidL[o] = make_uint2(bf16x2_lo(v0, v1, h0), bf16x2_lo(v2, v3, h1));
    }
    __syncthreads();

    float acc[2][4][4];

    // ---- GEMM2: hid @ We2 (3-term) ----
    ZACC(acc);
    mma3<8>(hidHa, hidLa, SH, g_Bf2, acc, m0, ntb, lane);
    // epilogue: ef bf16 hi -> SMEM; hagg scatter straight from registers
#pragma unroll
    for (int mt = 0; mt < 2; mt++) {
        int ra = m0 + mt * 16 + g, rb = ra + 8;
        size_t na = (size_t)s_row[ra] * 128, nb = (size_t)s_row[rb] * 128;
#pragma unroll
        for (int nt = 0; nt < 4; nt++) {
            int col = (ntb + nt) * 8 + 2 * tig;
            int uc  = (ntb + nt) * 4 + tig;
            float b0 = s_be2[col], b1 = s_be2[col + 1];
            float v0 = silu_f(acc[mt][nt][0] + b0), v1 = silu_f(acc[mt][nt][1] + b1);
            float v2 = silu_f(acc[mt][nt][2] + b0), v3 = silu_f(acc[mt][nt][3] + b1);
            efH[ra * SH + uc] = bf16x2_rn(v0, v1);
            efH[rb * SH + uc] = bf16x2_rn(v2, v3);
            red_v2(&g_hagg[na + col], v0, v1);
            red_v2(&g_hagg[nb + col], v2, v3);
        }
    }
    __syncthreads();

    // ---- GEMM3: ef @ Wc1 (1-term, coord path) ----
    ZACC(acc);
    mma1t<8>(efHa, SH, g_Bf3, acc, m0, ntb, lane);
    {
        float p[4] = {0.f, 0.f, 0.f, 0.f};
#pragma unroll
        for (int mt = 0; mt < 2; mt++) {
#pragma unroll
            for (int nt = 0; nt < 4; nt++) {
                int col = (ntb + nt) * 8 + 2 * tig;
                float b0 = s_bc1[col], b1 = s_bc1[col + 1];
                float w0 = s_wc2[col], w1 = s_wc2[col + 1];
                p[mt*2+0] += silu_f(acc[mt][nt][0] + b0) * w0
                           + silu_f(acc[mt][nt][1] + b1) * w1;
                p[mt*2+1] += silu_f(acc[mt][nt][2] + b0) * w0
                           + silu_f(acc[mt][nt][3] + b1) * w1;
            }
        }
#pragma unroll
        for (int i = 0; i < 4; i++) {
            p[i] += __shfl_xor_sync(0xffffffffu, p[i], 1);
            p[i] += __shfl_xor_sync(0xffffffffu, p[i], 2);
        }
        if (tig == 0) {
#pragma unroll
            for (int mt = 0; mt < 2; mt++) {
                s_part[nw * 64 + m0 + mt * 16 + g]     = p[mt*2+0];
                s_part[nw * 64 + m0 + mt * 16 + g + 8] = p[mt*2+1];
            }
        }
    }
    __syncthreads();

    if (tid < 64) {
        float s = s_part[tid] + s_part[64 + tid] + s_part[128 + tid] + s_part[192 + tid];
        float4 v = make_float4(s_diff[tid*3+0] * s, s_diff[tid*3+1] * s,
                               s_diff[tid*3+2] * s, 1.0f);
        red_v4(&g_cagg4[s_row[tid] * 4], v);
    }
}

// ---------------- node kernel: bf16 mma ----------------
#define SHN 132
#define NOFF_AHI 0
#define NOFF_ALO 8448
#define NOFF_HH  16896
#define NOFF_HL  21248
#define NOFF_MISC 25600
#define SMEM_NODE_U32 (NOFF_MISC + 256)
#define SMEM_NODE_BYTES (SMEM_NODE_U32 * 4)

__global__ void __launch_bounds__(TE, 1)
node_mma_kernel(const float* __restrict__ h, const float* __restrict__ y,
                const float* __restrict__ bn1, const float* __restrict__ bn2,
                float* __restrict__ out_h, float* __restrict__ out_y)
{
    extern __shared__ u32 smu[];
    u32* AhiN = smu + NOFF_AHI;
    u32* AloN = smu + NOFF_ALO;
    u32* hidH = smu + NOFF_HH;
    u32* hidL = smu + NOFF_HL;
    float* s_bn1 = (float*)(smu + NOFF_MISC);
    float* s_bn2 = s_bn1 + 128;

    const int tid  = threadIdx.x;
    const int lane = tid & 31;
    const int wid  = tid >> 5;
    const int g    = lane >> 2;
    const int tig  = lane & 3;
    const int mw   = wid >> 2;
    const int nw   = wid & 3;
    const int m0   = mw * 32;
    const int ntb  = nw * 4;
    const int n0   = blockIdx.x * 64;

    const u32 smb = smem_u32(smu);
    const u32 AhiA = smb + NOFF_AHI * 4;
    const u32 AloA = smb + NOFF_ALO * 4;
    const u32 hHa  = smb + NOFF_HH * 4;
    const u32 hLa  = smb + NOFF_HL * 4;

    if (tid < 128) { s_bn1[tid] = bn1[tid]; s_bn2[tid] = bn2[tid]; }

    for (int t = wid; t < 128; t += 8) {
        int r = t >> 1, half = t & 1, n = n0 + r;
        float4 v = make_float4(0.f, 0.f, 0.f, 0.f);
        if (n < N_NODES) {
            const float* src = half ? (g_hagg + (size_t)n * 128) : (h + (size_t)n * 128);
            v = __ldg((const float4*)src + lane);
        }
        u32 h0 = bf16x2_rn(v.x, v.y), h1 = bf16x2_rn(v.z, v.w);
        int o = r * SHN + half * 64 + lane * 2;
        *(uint2*)&AhiN[o] = make_uint2(h0, h1);
        *(uint2*)&AloN[o] = make_uint2(bf16x2_lo(v.x, v.y, h0), bf16x2_lo(v.z, v.w, h1));
    }
    __syncthreads();

    float acc[2][4][4];

    ZACC(acc);
    mma3<16>(AhiA, AloA, SHN, g_Bfn1, acc, m0, ntb, lane);
#pragma unroll
    for (int mt = 0; mt < 2; mt++) {
        int ra = m0 + mt * 16 + g, rb = ra + 8;
#pragma unroll
        for (int nt = 0; nt < 4; nt++) {
            int col = (ntb + nt) * 8 + 2 * tig;
            int uc  = (ntb + nt) * 4 + tig;
            float b0 = s_bn1[col], b1 = s_bn1[col + 1];
            float v0 = silu_f(acc[mt][nt][0] + b0), v1 = silu_f(acc[mt][nt][1] + b1);
            float v2 = silu_f(acc[mt][nt][2] + b0), v3 = silu_f(acc[mt][nt][3] + b1);
            u32 ha = bf16x2_rn(v0, v1), hb = bf16x2_rn(v2, v3);
            hidH[ra * SH + uc] = ha; hidL[ra * SH + uc] = bf16x2_lo(v0, v1, ha);
            hidH[rb * SH + uc] = hb; hidL[rb * SH + uc] = bf16x2_lo(v2, v3, hb);
        }
    }
    __syncthreads();

    ZACC(acc);
    mma3<8>(hHa, hLa, SH, g_Bfn2, acc, m0, ntb, lane);
#pragma unroll
    for (int mt = 0; mt < 2; mt++) {
        int ra = m0 + mt * 16 + g, rb = ra + 8;
        int na = n0 + ra, nb = n0 + rb;
#pragma unroll
        for (int nt = 0; nt < 4; nt++) {
            int col = (ntb + nt) * 8 + 2 * tig;
            float b0 = s_bn2[col], b1 = s_bn2[col + 1];
            if (na < N_NODES) {
                float2 hh = __ldg((const float2*)(h + (size_t)na * 128 + col));
                *(float2*)&out_h[(size_t)na * 128 + col] =
                    make_float2(acc[mt][nt][0] + b0 + hh.x, acc[mt][nt][1] + b1 + hh.y);
            }
            if (nb < N_NODES) {
                float2 hh = __ldg((const float2*)(h + (size_t)nb * 128 + col));
                *(float2*)&out_h[(size_t)nb * 128 + col] =
                    make_float2(acc[mt][nt][2] + b0 + hh.x, acc[mt][nt][3] + b1 + hh.y);
            }
        }
    }

    if (tid < 64) {
        int n = n0 + tid;
        if (n < N_NODES) {
            float c = g_cagg4[n * 4 + 3]; c = (c < 1.0f) ? 1.0f : c;
            out_y[n*3+0] = y[n*3+0] + g_cagg4[n*4+0] / c;
            out_y[n*3+1] = y[n*3+1] + g_cagg4[n*4+1] / c;
            out_y[n*3+2] = y[n*3+2] + g_cagg4[n*4+2] / c;
        }
    }
}

extern "C" void kernel_launch(void* const* d_in, const int* in_sizes, int n_in,
                              void* d_out, int out_size)
{
    const float* h   = (const float*)d_in[0];
    const float* y   = (const float*)d_in[1];
    const int*   ei  = (const int*)d_in[2];
    const float* We1 = (const float*)d_in[3];
    const float* be1 = (const float*)d_in[4];
    const float* We2 = (const float*)d_in[5];
    const float* be2 = (const float*)d_in[6];
    const float* Wc1 = (const float*)d_in[7];
    const float* bc1 = (const float*)d_in[8];
    const float* Wc2 = (const float*)d_in[9];
    const float* Wn1 = (const float*)d_in[10];
    const float* bn1 = (const float*)d_in[11];
    const float* Wn2 = (const float*)d_in[12];
    const float* bn2 = (const float*)d_in[13];

    float* out_h = (float*)d_out;
    float* out_y = out_h + (size_t)N_NODES * 128;

    cudaFuncSetAttribute(edge_kernel, cudaFuncAttributeMaxDynamicSharedMemorySize,
                         SMEM_EDGE_BYTES);
    cudaFuncSetAttribute(node_mma_kernel, cudaFuncAttributeMaxDynamicSharedMemorySize,
                         SMEM_NODE_BYTES);
    cudaFuncSetAttribute(pre_kernel, cudaFuncAttributeMaxDynamicSharedMemorySize,
                         PRE_SMEM_BYTES);

    zero_kernel<<<512, TE>>>();
    prep_kernel<<<80, 256>>>(We2, Wc1, Wn1, Wn2);
    pre_kernel<<<(N_NODES + 63) / 64, TN, PRE_SMEM_BYTES>>>(h, We1, be1);

    edge_kernel<<<N_EDGES / 64, TE, SMEM_EDGE_BYTES>>>(
        y, ei, We1 + 256 * 128, be2, bc1, Wc2);

    node_mma_kernel<<<(N_NODES + 63) / 64, TE, SMEM_NODE_BYTES>>>(
        h, y, bn1, bn2, out_h, out_y);
}